// round 15
// baseline (speedup 1.0000x reference)
#include <cuda_runtime.h>
#include <cuda_fp16.h>
#include <cstdint>

#define N_NODES 50000
#define IN_DIM  256
#define HID     128
#define OUT_DIM 64
#define E_MAX   800000
#define CSR_BLOCKS 49   // ceil(N/1024); must be <= SM count (single-wave resident)

// Scratch (device globals)
__device__ float  g_h  [(size_t)N_NODES * HID];
__device__ float  g_h2 [(size_t)N_NODES * HID];
__device__ __half g_hh [(size_t)N_NODES * HID];   // fp16 gather mirror A
__device__ __half g_hh2[(size_t)N_NODES * HID];   // fp16 gather mirror B
__device__ float  g_s1a[N_NODES], g_s2a[N_NODES];
__device__ float  g_s1b[N_NODES], g_s2b[N_NODES];
__device__ int    g_is64;
__device__ int    g_deg[N_NODES + 2];             // [N], [N+1] = grid-sync counters
__device__ int    g_rowptr[N_NODES + 1];
__device__ int    g_cursor[N_NODES];
__device__ int    g_bsum[64];
__device__ int    g_src_sorted[E_MAX];

// ---- f32x2 helpers ----
__device__ __forceinline__ unsigned long long pack2(float lo, float hi) {
    unsigned long long p;
    asm("mov.b64 %0, {%1, %2};" : "=l"(p) : "f"(lo), "f"(hi));
    return p;
}
__device__ __forceinline__ void unpack2(unsigned long long p, float& lo, float& hi) {
    asm("mov.b64 {%0, %1}, %2;" : "=f"(lo), "=f"(hi) : "l"(p));
}
__device__ __forceinline__ void fma2(unsigned long long& d, unsigned long long a,
                                     unsigned long long b) {
    asm("fma.rn.f32x2 %0, %1, %2, %0;" : "+l"(d) : "l"(a), "l"(b));
}

__device__ __forceinline__ float2 h2_to_f2(unsigned u) {
    __half2 h = *reinterpret_cast<__half2*>(&u);
    return __half22float2(h);
}

__device__ __forceinline__ int edge_row(const int* ei32, int e, int E) {
    return g_is64 ? ei32[2 * e] : ei32[e];
}
__device__ __forceinline__ int edge_col(const int* ei32, int e, int E) {
    return g_is64 ? ei32[2 * (E + e)] : ei32[E + e];
}

// ---------------------------------------------------------------------------
// dtype probe: one 128-thread block.
// ---------------------------------------------------------------------------
__global__ void detect_kernel(const int* __restrict__ ei32, int n32) {
    const int t = threadIdx.x;
    int idx = (1 + (int)(((long long)t * (n32 - 2)) / 128)) | 1;
    int nz = (ei32[idx] != 0) ? 1 : 0;
    int any = __syncthreads_or(nz);
    if (t == 0) g_is64 = any ? 0 : 1;
}

__global__ void hist_kernel(const int* __restrict__ ei32, int E) {
    int e = blockIdx.x * blockDim.x + threadIdx.x;
    if (e >= E) return;
    int col = edge_col(ei32, e, E);
    if ((unsigned)col < N_NODES) atomicAdd(&g_deg[col], 1);
}

// ---------------------------------------------------------------------------
// csr_build: fused scan_partial + spine/fixup + scatter, one kernel.
// 49 blocks x 1024 threads -- all resident (49 < 148 SMs) so atomic-counter
// grid barriers are deadlock-free. Counters in g_deg[N], g_deg[N+1] (memset 0).
// ---------------------------------------------------------------------------
__global__ void __launch_bounds__(1024) csr_build_kernel(const int* __restrict__ ei32,
                                                         int n, int E) {
    __shared__ int wsum[32];
    __shared__ int boff_s;
    const int tid = threadIdx.x;
    const int b   = blockIdx.x;
    const int gid = b * 1024 + tid;
    const int lane = tid & 31, wid = tid >> 5;

    // ---- Phase A: per-block exclusive scan of g_deg ----
    int v = (gid < n) ? g_deg[gid] : 0;
    int inc = v;
    #pragma unroll
    for (int o = 1; o < 32; o <<= 1) {
        int t = __shfl_up_sync(0xffffffffu, inc, o);
        if (lane >= o) inc += t;
    }
    if (lane == 31) wsum[wid] = inc;
    __syncthreads();
    if (tid < 32) {
        int w = wsum[tid];
        int wi = w;
        #pragma unroll
        for (int o = 1; o < 32; o <<= 1) {
            int t = __shfl_up_sync(0xffffffffu, wi, o);
            if (tid >= o) wi += t;
        }
        wsum[tid] = wi - w;
    }
    __syncthreads();
    int exc = inc - v + wsum[wid];
    if (tid == 1023) g_bsum[b] = exc + v;

    // grid barrier 1
    __threadfence();
    __syncthreads();
    if (tid == 0) {
        atomicAdd(&g_deg[N_NODES], 1);
        while (atomicAdd(&g_deg[N_NODES], 0) < CSR_BLOCKS) { }
    }
    __syncthreads();

    // ---- Phase B: spine offset (block-local reduce of bsum[0..b-1]) + apply ----
    if (tid < 32) {
        int s = 0;
        if (tid < b)      s += g_bsum[tid];
        if (tid + 32 < b) s += g_bsum[tid + 32];
        #pragma unroll
        for (int o = 16; o > 0; o >>= 1)
            s += __shfl_down_sync(0xffffffffu, s, o);
        if (tid == 0) boff_s = s;
    }
    __syncthreads();
    if (gid < n) {
        int r = exc + boff_s;
        g_rowptr[gid] = r;
        g_cursor[gid] = r;
    }
    if (gid == 0) g_rowptr[n] = E;

    // grid barrier 2
    __threadfence();
    __syncthreads();
    if (tid == 0) {
        atomicAdd(&g_deg[N_NODES + 1], 1);
        while (atomicAdd(&g_deg[N_NODES + 1], 0) < CSR_BLOCKS) { }
    }
    __syncthreads();

    // ---- Phase C: scatter (grid-stride over edges) ----
    const int stride = CSR_BLOCKS * 1024;
    for (int e = gid; e < E; e += stride) {
        int row = edge_row(ei32, e, E);
        int col = edge_col(ei32, e, E);
        if ((unsigned)row >= N_NODES || (unsigned)col >= N_NODES) continue;
        int pos = atomicAdd(&g_cursor[col], 1);
        g_src_sorted[pos] = row;
    }
}

// ---------------------------------------------------------------------------
// GEMM0 + fused node_prep: 128 thr, 16 rows/block, f32x2. (R13-proven)
// ---------------------------------------------------------------------------
#define G0_ROWS 16
#define G0_PAD  18
__global__ void __launch_bounds__(128) gemm0_kernel(const float* __restrict__ x,
                                                    const float* __restrict__ W0,
                                                    const float* __restrict__ b0,
                                                    const float* __restrict__ att_w,
                                                    const float* __restrict__ att_b) {
    __shared__ float xs[IN_DIM * G0_PAD];     // 18 KB; reused for epilogue
    const int tid  = threadIdx.x;
    const int lane = tid & 31, wid = tid >> 5;
    const int row0 = blockIdx.x * G0_ROWS;

    const float* xsrc = x + (size_t)row0 * IN_DIM;
    #pragma unroll
    for (int i = 0; i < G0_ROWS * IN_DIM / 128; i++) {
        int idx = tid + i * 128;
        xs[(idx & 255) * G0_PAD + (idx >> 8)] = xsrc[idx];
    }
    __syncthreads();

    unsigned long long acc[G0_ROWS / 2];
    #pragma unroll
    for (int r = 0; r < G0_ROWS / 2; r++) acc[r] = 0ull;

    #pragma unroll 4
    for (int k = 0; k < IN_DIM; k++) {
        const float w = W0[k * HID + tid];
        const unsigned long long w2 = pack2(w, w);
        const unsigned long long* xp = (const unsigned long long*)(xs + k * G0_PAD);
        #pragma unroll
        for (int rp = 0; rp < G0_ROWS / 2; rp++) fma2(acc[rp], xp[rp], w2);
    }

    const float bias = b0[tid];
    float hv[G0_ROWS];
    #pragma unroll
    for (int rp = 0; rp < G0_ROWS / 2; rp++) {
        float lo, hi;
        unpack2(acc[rp], lo, hi);
        lo += bias; hi += bias;
        hv[2 * rp]     = lo > 0.f ? lo : 0.f;
        hv[2 * rp + 1] = hi > 0.f ? hi : 0.f;
        g_h[(size_t)(row0 + 2 * rp)     * HID + tid] = hv[2 * rp];
        g_h[(size_t)(row0 + 2 * rp + 1) * HID + tid] = hv[2 * rp + 1];
        g_hh[(size_t)(row0 + 2 * rp)     * HID + tid] = __float2half_rn(hv[2 * rp]);
        g_hh[(size_t)(row0 + 2 * rp + 1) * HID + tid] = __float2half_rn(hv[2 * rp + 1]);
    }

    // epilogue: transpose into smem, per-warp attention dots (4 rows/warp)
    __syncthreads();
    #pragma unroll
    for (int r = 0; r < G0_ROWS; r++)
        xs[r * 128 + tid] = hv[r];
    __syncthreads();

    const float ab = att_b[0];
    #pragma unroll
    for (int r4 = 0; r4 < 4; r4++) {
        const int r = wid * 4 + r4;
        const float* hr = xs + r * 128;
        float v0 = hr[lane], v1 = hr[lane + 32], v2 = hr[lane + 64], v3 = hr[lane + 96];
        float s1 = v0 * att_w[lane] + v1 * att_w[lane + 32]
                 + v2 * att_w[lane + 64] + v3 * att_w[lane + 96];
        float s2 = v0 * att_w[HID + lane] + v1 * att_w[HID + lane + 32]
                 + v2 * att_w[HID + lane + 64] + v3 * att_w[HID + lane + 96];
        #pragma unroll
        for (int off = 16; off > 0; off >>= 1) {
            s1 += __shfl_down_sync(0xffffffffu, s1, off);
            s2 += __shfl_down_sync(0xffffffffu, s2, off);
        }
        if (lane == 0) { g_s1a[row0 + r] = s1; g_s2a[row0 + r] = s2 + ab; }
    }
}

// ---------------------------------------------------------------------------
// agg kernel (byte-identical to R13): warp per destination, fp16 gathers,
// in-loop alpha, fp32 accumulation + epilogue. 64-thr blocks.
// ---------------------------------------------------------------------------
template <bool NEXT>
__global__ void __launch_bounds__(64) agg_kernel(const float* __restrict__ hsrc,
                                                 float* __restrict__ hdst,
                                                 const __half* __restrict__ hhsrc,
                                                 __half* __restrict__ hhdst,
                                                 const float* __restrict__ s1in,
                                                 const float* __restrict__ s2in,
                                                 float* __restrict__ s1out,
                                                 float* __restrict__ s2out,
                                                 const float* __restrict__ eps_p,
                                                 const float* __restrict__ att_w,
                                                 const float* __restrict__ att_b) {
    const int d = (blockIdx.x * 64 + threadIdx.x) >> 5;
    if (d >= N_NODES) return;
    const int lane = threadIdx.x & 31;

    const float s2b = s2in[d];
    const int start = g_rowptr[d];
    const int end   = g_rowptr[d + 1];

    float4 acc = make_float4(0.f, 0.f, 0.f, 0.f);
    for (int base = start; base < end; base += 32) {
        const int cnt = min(32, end - base);
        const int li = base + ((lane < cnt) ? lane : 0);
        const int srcl = g_src_sorted[li];
        const float al = tanhf(s1in[srcl] + s2b);

        int j = 0;
        for (; j + 4 <= cnt; j += 4) {
            int s0 = __shfl_sync(0xffffffffu, srcl, j);
            int s1_ = __shfl_sync(0xffffffffu, srcl, j + 1);
            int s2_ = __shfl_sync(0xffffffffu, srcl, j + 2);
            int s3 = __shfl_sync(0xffffffffu, srcl, j + 3);
            float a0 = __shfl_sync(0xffffffffu, al, j);
            float a1 = __shfl_sync(0xffffffffu, al, j + 1);
            float a2 = __shfl_sync(0xffffffffu, al, j + 2);
            float a3 = __shfl_sync(0xffffffffu, al, j + 3);
            uint2 p0 = ((const uint2*)(hhsrc + (size_t)s0  * HID))[lane];
            uint2 p1 = ((const uint2*)(hhsrc + (size_t)s1_ * HID))[lane];
            uint2 p2 = ((const uint2*)(hhsrc + (size_t)s2_ * HID))[lane];
            uint2 p3 = ((const uint2*)(hhsrc + (size_t)s3  * HID))[lane];
            float2 f;
            f = h2_to_f2(p0.x); acc.x = fmaf(a0, f.x, acc.x); acc.y = fmaf(a0, f.y, acc.y);
            f = h2_to_f2(p0.y); acc.z = fmaf(a0, f.x, acc.z); acc.w = fmaf(a0, f.y, acc.w);
            f = h2_to_f2(p1.x); acc.x = fmaf(a1, f.x, acc.x); acc.y = fmaf(a1, f.y, acc.y);
            f = h2_to_f2(p1.y); acc.z = fmaf(a1, f.x, acc.z); acc.w = fmaf(a1, f.y, acc.w);
            f = h2_to_f2(p2.x); acc.x = fmaf(a2, f.x, acc.x); acc.y = fmaf(a2, f.y, acc.y);
            f = h2_to_f2(p2.y); acc.z = fmaf(a2, f.x, acc.z); acc.w = fmaf(a2, f.y, acc.w);
            f = h2_to_f2(p3.x); acc.x = fmaf(a3, f.x, acc.x); acc.y = fmaf(a3, f.y, acc.y);
            f = h2_to_f2(p3.y); acc.z = fmaf(a3, f.x, acc.z); acc.w = fmaf(a3, f.y, acc.w);
        }
        for (; j < cnt; j++) {
            int s0 = __shfl_sync(0xffffffffu, srcl, j);
            float a0 = __shfl_sync(0xffffffffu, al, j);
            uint2 p0 = ((const uint2*)(hhsrc + (size_t)s0 * HID))[lane];
            float2 f;
            f = h2_to_f2(p0.x); acc.x = fmaf(a0, f.x, acc.x); acc.y = fmaf(a0, f.y, acc.y);
            f = h2_to_f2(p0.y); acc.z = fmaf(a0, f.x, acc.z); acc.w = fmaf(a0, f.y, acc.w);
        }
    }

    const float eps = eps_p[0];
    const float ome = 1.f - eps;
    const float4 ho = ((const float4*)(hsrc + (size_t)d * HID))[lane];
    float4 hn;
    hn.x = fmaf(eps, ho.x, ome * acc.x); hn.x = hn.x > 0.f ? hn.x : 0.f;
    hn.y = fmaf(eps, ho.y, ome * acc.y); hn.y = hn.y > 0.f ? hn.y : 0.f;
    hn.z = fmaf(eps, ho.z, ome * acc.z); hn.z = hn.z > 0.f ? hn.z : 0.f;
    hn.w = fmaf(eps, ho.w, ome * acc.w); hn.w = hn.w > 0.f ? hn.w : 0.f;
    ((float4*)(hdst + (size_t)d * HID))[lane] = hn;

    if (NEXT) {
        __half2 q01 = __floats2half2_rn(hn.x, hn.y);
        __half2 q23 = __floats2half2_rn(hn.z, hn.w);
        uint2 pk;
        pk.x = *reinterpret_cast<unsigned*>(&q01);
        pk.y = *reinterpret_cast<unsigned*>(&q23);
        ((uint2*)(hhdst + (size_t)d * HID))[lane] = pk;

        const float4 w1 = ((const float4*)att_w)[lane];
        const float4 w2 = ((const float4*)(att_w + HID))[lane];
        float s1 = hn.x * w1.x + hn.y * w1.y + hn.z * w1.z + hn.w * w1.w;
        float s2 = hn.x * w2.x + hn.y * w2.y + hn.z * w2.z + hn.w * w2.w;
        #pragma unroll
        for (int off = 16; off > 0; off >>= 1) {
            s1 += __shfl_down_sync(0xffffffffu, s1, off);
            s2 += __shfl_down_sync(0xffffffffu, s2, off);
        }
        if (lane == 0) { s1out[d] = s1; s2out[d] = s2 + att_b[0]; }
    }
}

// ---------------------------------------------------------------------------
// GEMMC (R13-proven): out = g_h @ Wc + bc. 64 thr, 16 rows/block, f32x2.
// ---------------------------------------------------------------------------
#define GC_ROWS 16
#define GC_PAD  18
__global__ void __launch_bounds__(64) gemmc_kernel(const float* __restrict__ Wc,
                                                   const float* __restrict__ bc,
                                                   float* __restrict__ out) {
    __shared__ float hs[HID * GC_PAD];   // 9 KB
    const int tid  = threadIdx.x;
    const int row0 = blockIdx.x * GC_ROWS;

    const float* hsrc = g_h + (size_t)row0 * HID;
    #pragma unroll
    for (int i = 0; i < GC_ROWS * HID / 64; i++) {
        int idx = tid + i * 64;
        hs[(idx & 127) * GC_PAD + (idx >> 7)] = hsrc[idx];
    }
    __syncthreads();

    unsigned long long acc[GC_ROWS / 2];
    #pragma unroll
    for (int r = 0; r < GC_ROWS / 2; r++) acc[r] = 0ull;

    #pragma unroll 4
    for (int k = 0; k < HID; k++) {
        const float w = Wc[k * OUT_DIM + tid];
        const unsigned long long w2 = pack2(w, w);
        const unsigned long long* hp = (const unsigned long long*)(hs + k * GC_PAD);
        #pragma unroll
        for (int rp = 0; rp < GC_ROWS / 2; rp++) fma2(acc[rp], hp[rp], w2);
    }

    const float bias = bc[tid];
    #pragma unroll
    for (int rp = 0; rp < GC_ROWS / 2; rp++) {
        float lo, hi;
        unpack2(acc[rp], lo, hi);
        out[(size_t)(row0 + 2 * rp)     * OUT_DIM + tid] = lo + bias;
        out[(size_t)(row0 + 2 * rp + 1) * OUT_DIM + tid] = hi + bias;
    }
}

// ---------------------------------------------------------------------------
extern "C" void kernel_launch(void* const* d_in, const int* in_sizes, int n_in,
                              void* d_out, int out_size) {
    const float* x    = (const float*)d_in[0];
    const int*   ei32 = (const int*)d_in[1];
    const float* W0   = (const float*)d_in[2];
    const float* b0   = (const float*)d_in[3];
    const float* aw1  = (const float*)d_in[4];
    const float* ab1  = (const float*)d_in[5];
    const float* eps1 = (const float*)d_in[6];
    const float* aw2  = (const float*)d_in[7];
    const float* ab2  = (const float*)d_in[8];
    const float* eps2 = (const float*)d_in[9];
    const float* Wc   = (const float*)d_in[10];
    const float* bc   = (const float*)d_in[11];
    float*       out  = (float*)d_out;

    const int E = in_sizes[1] / 2;
    const int agg_blocks = (N_NODES + 1) / 2;    // 64-thr blocks, 2 dests each

    float *d_g_h, *d_g_h2, *d_s1a, *d_s2a, *d_s1b, *d_s2b;
    __half *d_hh, *d_hh2;
    int* d_deg;
    cudaGetSymbolAddress((void**)&d_g_h,  g_h);
    cudaGetSymbolAddress((void**)&d_g_h2, g_h2);
    cudaGetSymbolAddress((void**)&d_hh,   g_hh);
    cudaGetSymbolAddress((void**)&d_hh2,  g_hh2);
    cudaGetSymbolAddress((void**)&d_s1a, g_s1a);
    cudaGetSymbolAddress((void**)&d_s2a, g_s2a);
    cudaGetSymbolAddress((void**)&d_s1b, g_s1b);
    cudaGetSymbolAddress((void**)&d_s2b, g_s2b);
    cudaGetSymbolAddress((void**)&d_deg, g_deg);

    // Fork-join: gemm0 (stream s2) overlaps the CSR build chain.
    cudaStream_t s2;
    cudaEvent_t ev0, ev1;
    cudaStreamCreateWithFlags(&s2, cudaStreamNonBlocking);
    cudaEventCreateWithFlags(&ev0, cudaEventDisableTiming);
    cudaEventCreateWithFlags(&ev1, cudaEventDisableTiming);

    cudaEventRecord(ev0, 0);
    cudaStreamWaitEvent(s2, ev0, 0);
    gemm0_kernel<<<N_NODES / G0_ROWS, 128, 0, s2>>>(x, W0, b0, aw1, ab1);
    cudaEventRecord(ev1, s2);

    // CSR chain on default stream (independent of gemm0)
    cudaMemsetAsync(d_deg, 0, (N_NODES + 2) * sizeof(int), 0);  // deg + sync ctrs
    detect_kernel<<<1, 128>>>(ei32, in_sizes[1]);
    hist_kernel<<<(E + 255) / 256, 256>>>(ei32, E);
    csr_build_kernel<<<CSR_BLOCKS, 1024>>>(ei32, N_NODES, E);

    cudaStreamWaitEvent(0, ev1, 0);          // join: agg1 needs s1a/s2a

    agg_kernel<true ><<<agg_blocks, 64>>>(d_g_h,  d_g_h2, d_hh,  d_hh2,
                                          d_s1a, d_s2a, d_s1b, d_s2b,
                                          eps1, aw2, ab2);
    agg_kernel<false><<<agg_blocks, 64>>>(d_g_h2, d_g_h,  d_hh2, nullptr,
                                          d_s1b, d_s2b, nullptr, nullptr,
                                          eps2, nullptr, nullptr);
    gemmc_kernel<<<N_NODES / GC_ROWS, 64>>>(Wc, bc, out);
}

// round 16
// speedup vs baseline: 1.1630x; 1.1630x over previous
#include <cuda_runtime.h>
#include <cuda_fp16.h>
#include <cstdint>

#define N_NODES 50000
#define IN_DIM  256
#define HID     128
#define OUT_DIM 64
#define E_MAX   800000

// Scratch (device globals)
__device__ float  g_h  [(size_t)N_NODES * HID];   // fp32 final h (for gemmc only)
__device__ __half g_hh [(size_t)N_NODES * HID];   // fp16 h layer A
__device__ __half g_hh2[(size_t)N_NODES * HID];   // fp16 h layer B
__device__ float  g_s1a[N_NODES], g_s2a[N_NODES];
__device__ float  g_s1b[N_NODES], g_s2b[N_NODES];
__device__ int    g_is64;
__device__ int    g_deg[N_NODES];
__device__ int    g_rowptr[N_NODES + 1];
__device__ int    g_cursor[N_NODES];
__device__ int    g_bsum[64];
__device__ int    g_src_sorted[E_MAX];

// ---- f32x2 helpers ----
__device__ __forceinline__ unsigned long long pack2(float lo, float hi) {
    unsigned long long p;
    asm("mov.b64 %0, {%1, %2};" : "=l"(p) : "f"(lo), "f"(hi));
    return p;
}
__device__ __forceinline__ void unpack2(unsigned long long p, float& lo, float& hi) {
    asm("mov.b64 {%0, %1}, %2;" : "=f"(lo), "=f"(hi) : "l"(p));
}
__device__ __forceinline__ void fma2(unsigned long long& d, unsigned long long a,
                                     unsigned long long b) {
    asm("fma.rn.f32x2 %0, %1, %2, %0;" : "+l"(d) : "l"(a), "l"(b));
}

__device__ __forceinline__ float2 h2_to_f2(unsigned u) {
    __half2 h = *reinterpret_cast<__half2*>(&u);
    return __half22float2(h);
}

__device__ __forceinline__ int edge_row(const int* ei32, int e, int E) {
    return g_is64 ? ei32[2 * e] : ei32[e];
}
__device__ __forceinline__ int edge_col(const int* ei32, int e, int E) {
    return g_is64 ? ei32[2 * (E + e)] : ei32[E + e];
}

// ---------------------------------------------------------------------------
// dtype probe: one 128-thread block (g_deg zeroed by memset node).
// ---------------------------------------------------------------------------
__global__ void detect_kernel(const int* __restrict__ ei32, int n32) {
    const int t = threadIdx.x;
    int idx = (1 + (int)(((long long)t * (n32 - 2)) / 128)) | 1;
    int nz = (ei32[idx] != 0) ? 1 : 0;
    int any = __syncthreads_or(nz);
    if (t == 0) g_is64 = any ? 0 : 1;
}

__global__ void hist_kernel(const int* __restrict__ ei32, int E) {
    int e = blockIdx.x * blockDim.x + threadIdx.x;
    if (e >= E) return;
    int col = edge_col(ei32, e, E);
    if ((unsigned)col < N_NODES) atomicAdd(&g_deg[col], 1);
}

// ---------------------------------------------------------------------------
// scan stage 1: per-1024-block exclusive scan; totals to g_bsum.
// ---------------------------------------------------------------------------
__global__ void __launch_bounds__(1024) scan_partial_kernel(int n) {
    __shared__ int wsum[32];
    const int tid = threadIdx.x;
    const int gid = blockIdx.x * 1024 + tid;
    const int lane = tid & 31, wid = tid >> 5;

    int v = (gid < n) ? g_deg[gid] : 0;
    int inc = v;
    #pragma unroll
    for (int o = 1; o < 32; o <<= 1) {
        int t = __shfl_up_sync(0xffffffffu, inc, o);
        if (lane >= o) inc += t;
    }
    if (lane == 31) wsum[wid] = inc;
    __syncthreads();
    if (tid < 32) {
        int w = wsum[tid];
        int wi = w;
        #pragma unroll
        for (int o = 1; o < 32; o <<= 1) {
            int t = __shfl_up_sync(0xffffffffu, wi, o);
            if (tid >= o) wi += t;
        }
        wsum[tid] = wi - w;
    }
    __syncthreads();
    int exc = inc - v + wsum[wid];
    if (gid < n) g_rowptr[gid] = exc;
    if (tid == 1023) g_bsum[blockIdx.x] = exc + v;
}

// ---------------------------------------------------------------------------
// scan fixup (inlines spine scan): each block sums bsum[0..bid-1] itself.
// ---------------------------------------------------------------------------
__global__ void __launch_bounds__(1024) scan_fixup_kernel(int n, int E) {
    __shared__ int boff_s;
    const int tid = threadIdx.x;
    if (tid < 32) {
        const int b = blockIdx.x;
        int v = 0;
        if (tid < b)      v += g_bsum[tid];
        if (tid + 32 < b) v += g_bsum[tid + 32];
        #pragma unroll
        for (int o = 16; o > 0; o >>= 1)
            v += __shfl_down_sync(0xffffffffu, v, o);
        if (tid == 0) boff_s = v;
    }
    __syncthreads();
    const int gid = blockIdx.x * 1024 + tid;
    if (gid < n) {
        int v = g_rowptr[gid] + boff_s;
        g_rowptr[gid] = v;
        g_cursor[gid] = v;
    }
    if (gid == 0) g_rowptr[n] = E;
}

// ---------------------------------------------------------------------------
// scatter_fill: CSR fill (src only) — independent of gemm0, overlapped.
// ---------------------------------------------------------------------------
__global__ void scatter_fill_kernel(const int* __restrict__ ei32, int E) {
    int e = blockIdx.x * blockDim.x + threadIdx.x;
    if (e >= E) return;
    int row = edge_row(ei32, e, E);
    int col = edge_col(ei32, e, E);
    if ((unsigned)row >= N_NODES || (unsigned)col >= N_NODES) return;
    int pos = atomicAdd(&g_cursor[col], 1);
    g_src_sorted[pos] = row;
}

// ---------------------------------------------------------------------------
// GEMM0 + fused node_prep: 128 thr, 16 rows/block, f32x2.
// Writes ONLY fp16 g_hh (fp32 h not needed until the final layer) + s1a/s2a.
// ---------------------------------------------------------------------------
#define G0_ROWS 16
#define G0_PAD  18
__global__ void __launch_bounds__(128) gemm0_kernel(const float* __restrict__ x,
                                                    const float* __restrict__ W0,
                                                    const float* __restrict__ b0,
                                                    const float* __restrict__ att_w,
                                                    const float* __restrict__ att_b) {
    __shared__ float xs[IN_DIM * G0_PAD];     // 18 KB; reused for epilogue
    const int tid  = threadIdx.x;
    const int lane = tid & 31, wid = tid >> 5;
    const int row0 = blockIdx.x * G0_ROWS;

    const float* xsrc = x + (size_t)row0 * IN_DIM;
    #pragma unroll
    for (int i = 0; i < G0_ROWS * IN_DIM / 128; i++) {
        int idx = tid + i * 128;
        xs[(idx & 255) * G0_PAD + (idx >> 8)] = xsrc[idx];
    }
    __syncthreads();

    unsigned long long acc[G0_ROWS / 2];
    #pragma unroll
    for (int r = 0; r < G0_ROWS / 2; r++) acc[r] = 0ull;

    #pragma unroll 4
    for (int k = 0; k < IN_DIM; k++) {
        const float w = W0[k * HID + tid];
        const unsigned long long w2 = pack2(w, w);
        const unsigned long long* xp = (const unsigned long long*)(xs + k * G0_PAD);
        #pragma unroll
        for (int rp = 0; rp < G0_ROWS / 2; rp++) fma2(acc[rp], xp[rp], w2);
    }

    const float bias = b0[tid];
    float hv[G0_ROWS];
    #pragma unroll
    for (int rp = 0; rp < G0_ROWS / 2; rp++) {
        float lo, hi;
        unpack2(acc[rp], lo, hi);
        lo += bias; hi += bias;
        hv[2 * rp]     = lo > 0.f ? lo : 0.f;
        hv[2 * rp + 1] = hi > 0.f ? hi : 0.f;
        g_hh[(size_t)(row0 + 2 * rp)     * HID + tid] = __float2half_rn(hv[2 * rp]);
        g_hh[(size_t)(row0 + 2 * rp + 1) * HID + tid] = __float2half_rn(hv[2 * rp + 1]);
    }

    // epilogue: transpose into smem, per-warp attention dots (4 rows/warp)
    __syncthreads();
    #pragma unroll
    for (int r = 0; r < G0_ROWS; r++)
        xs[r * 128 + tid] = hv[r];
    __syncthreads();

    const float ab = att_b[0];
    #pragma unroll
    for (int r4 = 0; r4 < 4; r4++) {
        const int r = wid * 4 + r4;
        const float* hr = xs + r * 128;
        float v0 = hr[lane], v1 = hr[lane + 32], v2 = hr[lane + 64], v3 = hr[lane + 96];
        float s1 = v0 * att_w[lane] + v1 * att_w[lane + 32]
                 + v2 * att_w[lane + 64] + v3 * att_w[lane + 96];
        float s2 = v0 * att_w[HID + lane] + v1 * att_w[HID + lane + 32]
                 + v2 * att_w[HID + lane + 64] + v3 * att_w[HID + lane + 96];
        #pragma unroll
        for (int off = 16; off > 0; off >>= 1) {
            s1 += __shfl_down_sync(0xffffffffu, s1, off);
            s2 += __shfl_down_sync(0xffffffffu, s2, off);
        }
        if (lane == 0) { g_s1a[row0 + r] = s1; g_s2a[row0 + r] = s2 + ab; }
    }
}

// ---------------------------------------------------------------------------
// agg kernel: warp per destination (natural order), fp16 gathers + fp16
// own-row read (eps term), fp32 accumulation + epilogue. 64-thr blocks.
// NEXT: writes fp16 hhdst + next-layer s1/s2.  !NEXT: writes fp32 hdst.
// ---------------------------------------------------------------------------
template <bool NEXT>
__global__ void __launch_bounds__(64) agg_kernel(float* __restrict__ hdst,
                                                 const __half* __restrict__ hhsrc,
                                                 __half* __restrict__ hhdst,
                                                 const float* __restrict__ s1in,
                                                 const float* __restrict__ s2in,
                                                 float* __restrict__ s1out,
                                                 float* __restrict__ s2out,
                                                 const float* __restrict__ eps_p,
                                                 const float* __restrict__ att_w,
                                                 const float* __restrict__ att_b) {
    const int d = (blockIdx.x * 64 + threadIdx.x) >> 5;
    if (d >= N_NODES) return;
    const int lane = threadIdx.x & 31;

    const float s2b = s2in[d];
    const int start = g_rowptr[d];
    const int end   = g_rowptr[d + 1];

    float4 acc = make_float4(0.f, 0.f, 0.f, 0.f);
    for (int base = start; base < end; base += 32) {
        const int cnt = min(32, end - base);
        const int li = base + ((lane < cnt) ? lane : 0);
        const int srcl = g_src_sorted[li];
        const float al = tanhf(s1in[srcl] + s2b);

        int j = 0;
        for (; j + 4 <= cnt; j += 4) {
            int s0 = __shfl_sync(0xffffffffu, srcl, j);
            int s1_ = __shfl_sync(0xffffffffu, srcl, j + 1);
            int s2_ = __shfl_sync(0xffffffffu, srcl, j + 2);
            int s3 = __shfl_sync(0xffffffffu, srcl, j + 3);
            float a0 = __shfl_sync(0xffffffffu, al, j);
            float a1 = __shfl_sync(0xffffffffu, al, j + 1);
            float a2 = __shfl_sync(0xffffffffu, al, j + 2);
            float a3 = __shfl_sync(0xffffffffu, al, j + 3);
            uint2 p0 = ((const uint2*)(hhsrc + (size_t)s0  * HID))[lane];
            uint2 p1 = ((const uint2*)(hhsrc + (size_t)s1_ * HID))[lane];
            uint2 p2 = ((const uint2*)(hhsrc + (size_t)s2_ * HID))[lane];
            uint2 p3 = ((const uint2*)(hhsrc + (size_t)s3  * HID))[lane];
            float2 f;
            f = h2_to_f2(p0.x); acc.x = fmaf(a0, f.x, acc.x); acc.y = fmaf(a0, f.y, acc.y);
            f = h2_to_f2(p0.y); acc.z = fmaf(a0, f.x, acc.z); acc.w = fmaf(a0, f.y, acc.w);
            f = h2_to_f2(p1.x); acc.x = fmaf(a1, f.x, acc.x); acc.y = fmaf(a1, f.y, acc.y);
            f = h2_to_f2(p1.y); acc.z = fmaf(a1, f.x, acc.z); acc.w = fmaf(a1, f.y, acc.w);
            f = h2_to_f2(p2.x); acc.x = fmaf(a2, f.x, acc.x); acc.y = fmaf(a2, f.y, acc.y);
            f = h2_to_f2(p2.y); acc.z = fmaf(a2, f.x, acc.z); acc.w = fmaf(a2, f.y, acc.w);
            f = h2_to_f2(p3.x); acc.x = fmaf(a3, f.x, acc.x); acc.y = fmaf(a3, f.y, acc.y);
            f = h2_to_f2(p3.y); acc.z = fmaf(a3, f.x, acc.z); acc.w = fmaf(a3, f.y, acc.w);
        }
        for (; j < cnt; j++) {
            int s0 = __shfl_sync(0xffffffffu, srcl, j);
            float a0 = __shfl_sync(0xffffffffu, al, j);
            uint2 p0 = ((const uint2*)(hhsrc + (size_t)s0 * HID))[lane];
            float2 f;
            f = h2_to_f2(p0.x); acc.x = fmaf(a0, f.x, acc.x); acc.y = fmaf(a0, f.y, acc.y);
            f = h2_to_f2(p0.y); acc.z = fmaf(a0, f.x, acc.z); acc.w = fmaf(a0, f.y, acc.w);
        }
    }

    // epilogue: eps term from own fp16 row (coalesced), fp32 math
    const float eps = eps_p[0];
    const float ome = 1.f - eps;
    uint2 po = ((const uint2*)(hhsrc + (size_t)d * HID))[lane];
    float2 ho01 = h2_to_f2(po.x);
    float2 ho23 = h2_to_f2(po.y);
    float4 hn;
    hn.x = fmaf(eps, ho01.x, ome * acc.x); hn.x = hn.x > 0.f ? hn.x : 0.f;
    hn.y = fmaf(eps, ho01.y, ome * acc.y); hn.y = hn.y > 0.f ? hn.y : 0.f;
    hn.z = fmaf(eps, ho23.x, ome * acc.z); hn.z = hn.z > 0.f ? hn.z : 0.f;
    hn.w = fmaf(eps, ho23.y, ome * acc.w); hn.w = hn.w > 0.f ? hn.w : 0.f;

    if (NEXT) {
        // fp16 h for the next layer
        __half2 q01 = __floats2half2_rn(hn.x, hn.y);
        __half2 q23 = __floats2half2_rn(hn.z, hn.w);
        uint2 pk;
        pk.x = *reinterpret_cast<unsigned*>(&q01);
        pk.y = *reinterpret_cast<unsigned*>(&q23);
        ((uint2*)(hhdst + (size_t)d * HID))[lane] = pk;

        const float4 w1 = ((const float4*)att_w)[lane];
        const float4 w2 = ((const float4*)(att_w + HID))[lane];
        float s1 = hn.x * w1.x + hn.y * w1.y + hn.z * w1.z + hn.w * w1.w;
        float s2 = hn.x * w2.x + hn.y * w2.y + hn.z * w2.z + hn.w * w2.w;
        #pragma unroll
        for (int off = 16; off > 0; off >>= 1) {
            s1 += __shfl_down_sync(0xffffffffu, s1, off);
            s2 += __shfl_down_sync(0xffffffffu, s2, off);
        }
        if (lane == 0) { s1out[d] = s1; s2out[d] = s2 + att_b[0]; }
    } else {
        // final layer: fp32 h for gemmc
        ((float4*)(hdst + (size_t)d * HID))[lane] = hn;
    }
}

// ---------------------------------------------------------------------------
// GEMMC: out = g_h @ Wc + bc. 64 thr, 16 rows/block, f32x2.
// ---------------------------------------------------------------------------
#define GC_ROWS 16
#define GC_PAD  18
__global__ void __launch_bounds__(64) gemmc_kernel(const float* __restrict__ Wc,
                                                   const float* __restrict__ bc,
                                                   float* __restrict__ out) {
    __shared__ float hs[HID * GC_PAD];   // 9 KB
    const int tid  = threadIdx.x;
    const int row0 = blockIdx.x * GC_ROWS;

    const float* hsrc = g_h + (size_t)row0 * HID;
    #pragma unroll
    for (int i = 0; i < GC_ROWS * HID / 64; i++) {
        int idx = tid + i * 64;
        hs[(idx & 127) * GC_PAD + (idx >> 7)] = hsrc[idx];
    }
    __syncthreads();

    unsigned long long acc[GC_ROWS / 2];
    #pragma unroll
    for (int r = 0; r < GC_ROWS / 2; r++) acc[r] = 0ull;

    #pragma unroll 4
    for (int k = 0; k < HID; k++) {
        const float w = Wc[k * OUT_DIM + tid];
        const unsigned long long w2 = pack2(w, w);
        const unsigned long long* hp = (const unsigned long long*)(hs + k * GC_PAD);
        #pragma unroll
        for (int rp = 0; rp < GC_ROWS / 2; rp++) fma2(acc[rp], hp[rp], w2);
    }

    const float bias = bc[tid];
    #pragma unroll
    for (int rp = 0; rp < GC_ROWS / 2; rp++) {
        float lo, hi;
        unpack2(acc[rp], lo, hi);
        out[(size_t)(row0 + 2 * rp)     * OUT_DIM + tid] = lo + bias;
        out[(size_t)(row0 + 2 * rp + 1) * OUT_DIM + tid] = hi + bias;
    }
}

// ---------------------------------------------------------------------------
extern "C" void kernel_launch(void* const* d_in, const int* in_sizes, int n_in,
                              void* d_out, int out_size) {
    const float* x    = (const float*)d_in[0];
    const int*   ei32 = (const int*)d_in[1];
    const float* W0   = (const float*)d_in[2];
    const float* b0   = (const float*)d_in[3];
    const float* aw1  = (const float*)d_in[4];
    const float* ab1  = (const float*)d_in[5];
    const float* eps1 = (const float*)d_in[6];
    const float* aw2  = (const float*)d_in[7];
    const float* ab2  = (const float*)d_in[8];
    const float* eps2 = (const float*)d_in[9];
    const float* Wc   = (const float*)d_in[10];
    const float* bc   = (const float*)d_in[11];
    float*       out  = (float*)d_out;

    const int E = in_sizes[1] / 2;
    const int agg_blocks  = (N_NODES + 1) / 2;        // 64-thr blocks, 2 dests each
    const int scan_blocks = (N_NODES + 1023) / 1024;  // 49

    float *d_g_h, *d_s1a, *d_s2a, *d_s1b, *d_s2b;
    __half *d_hh, *d_hh2;
    int* d_deg;
    cudaGetSymbolAddress((void**)&d_g_h,  g_h);
    cudaGetSymbolAddress((void**)&d_hh,   g_hh);
    cudaGetSymbolAddress((void**)&d_hh2,  g_hh2);
    cudaGetSymbolAddress((void**)&d_s1a, g_s1a);
    cudaGetSymbolAddress((void**)&d_s2a, g_s2a);
    cudaGetSymbolAddress((void**)&d_s1b, g_s1b);
    cudaGetSymbolAddress((void**)&d_s2b, g_s2b);
    cudaGetSymbolAddress((void**)&d_deg, g_deg);

    // Fork-join: gemm0 (stream s2) overlaps the full CSR build chain.
    cudaStream_t s2;
    cudaEvent_t ev0, ev1;
    cudaStreamCreateWithFlags(&s2, cudaStreamNonBlocking);
    cudaEventCreateWithFlags(&ev0, cudaEventDisableTiming);
    cudaEventCreateWithFlags(&ev1, cudaEventDisableTiming);

    cudaEventRecord(ev0, 0);
    cudaStreamWaitEvent(s2, ev0, 0);
    gemm0_kernel<<<N_NODES / G0_ROWS, 128, 0, s2>>>(x, W0, b0, aw1, ab1);
    cudaEventRecord(ev1, s2);

    // CSR chain on default stream (fully independent of gemm0)
    cudaMemsetAsync(d_deg, 0, N_NODES * sizeof(int), 0);
    detect_kernel<<<1, 128>>>(ei32, in_sizes[1]);
    hist_kernel<<<(E + 255) / 256, 256>>>(ei32, E);
    scan_partial_kernel<<<scan_blocks, 1024>>>(N_NODES);
    scan_fixup_kernel<<<scan_blocks, 1024>>>(N_NODES, E);
    scatter_fill_kernel<<<(E + 255) / 256, 256>>>(ei32, E);

    cudaStreamWaitEvent(0, ev1, 0);          // join: agg1 needs s1a/s2a

    agg_kernel<true ><<<agg_blocks, 64>>>(nullptr, d_hh,  d_hh2,
                                          d_s1a, d_s2a, d_s1b, d_s2b,
                                          eps1, aw2, ab2);
    agg_kernel<false><<<agg_blocks, 64>>>(d_g_h,  d_hh2, nullptr,
                                          d_s1b, d_s2b, nullptr, nullptr,
                                          eps2, nullptr, nullptr);
    gemmc_kernel<<<N_NODES / GC_ROWS, 64>>>(Wc, bc, out);
}